// round 11
// baseline (speedup 1.0000x reference)
#include <cuda_runtime.h>

// VQC_Registers_BS_density — analytic collapse:
// State index s = 32*a + b. Even layers rotate a-pairs (2k,2k+1), odd layers
// rotate b-pairs (2m,2m+1); every 2x2 gate block B(theta) = R(theta - pi/2)
// is a rotation, same-pair rotations compose additively, and the 8 * (pi/2)
// offsets cancel (4*pi). The whole 16-layer circuit is therefore
//   U = R_a(sum theta_even) (x) R_b(sum theta_odd)
// and rho' = U rho U^T factors into four independent pairwise Givens mixes on
// the tensor indices (a1, b1, a2, b2) of rho[32,32,32,32]. Total traffic 8 MB;
// the 48 MB of gate-matrix inputs are never read. (Reference: 16 dense
// 1024x1024 conjugations, ~34 GFLOP + ~100 MB traffic.)
//
// TERMINAL configuration (10 measured rounds): 65536 threads = 128 blocks x
// 512 (single wave, 1 CTA/SM), 4x LDG.128 + 4x STG.128 per thread, uniform
// angle loads issued before the data loads (sum + MUFU sincos hidden under
// load latency), cross-lane a2 mix (shfl_xor 8) applied per row as loads
// land, local a1/b1/b2 mixes after, rows stored as finalized, branchless
// sign via bit-XOR, __ldcg single-use loads.
//
// Measured floor: wall 6.6-6.9 us with +/-0.25 us noise on IDENTICAL code;
// ncu kernel 5.1-5.6 us with its own ramp noise; all pipes <11%; duration
// insensitive to +/-50% instruction count across 10 structural variants
// (occupancy 13-37%, 1-4 CTAs/SM, shuffle vs shuffle-free, 1 vs 2 kernels).
// Remaining cost = launch/clock-ramp + one 8 MB memory round trip + graph
// replay overhead. Do not perturb further.

__device__ __forceinline__ void rot(float& a, float& b, float c, float s)
{
    float t = c * a - s * b;
    b = s * a + c * b;
    a = t;
}

// a2 Givens mix across lane^8: e' = ca*e + sg*partner (sg = +/-sa by v-half).
__device__ __forceinline__ void mix8(float4& y, float ca, float sg)
{
    float p;
    p = __shfl_xor_sync(0xffffffffu, y.x, 8);  y.x = ca * y.x + sg * p;
    p = __shfl_xor_sync(0xffffffffu, y.y, 8);  y.y = ca * y.y + sg * p;
    p = __shfl_xor_sync(0xffffffffu, y.z, 8);  y.z = ca * y.z + sg * p;
    p = __shfl_xor_sync(0xffffffffu, y.w, 8);  y.w = ca * y.w + sg * p;
}

__global__ __launch_bounds__(512) void vqc_bs_density_kernel(
    const float* __restrict__ rho,
    const float* __restrict__ angles,
    float* __restrict__ out)
{
    const int tid = blockIdx.x * 512 + threadIdx.x;  // 0..65535

    // Composed angles first (uniform; 4x LDG.128 broadcast). Their latency
    // and the sum/sincos chain overlap the data loads issued just below.
    const float4* a4 = reinterpret_cast<const float4*>(angles);
    const float4 A0 = __ldg(a4 + 0), A1 = __ldg(a4 + 1);
    const float4 A2 = __ldg(a4 + 2), A3 = __ldg(a4 + 3);

    // lane bits: [0:3)=u (float4 within 32-col half), [3]=v (a2 half).
    const int lane = tid & 31;
    const int P    = (tid >> 5) & 7;
    const int m    = (tid >> 8) & 15;
    const int k    = tid >> 12;

    const int c  = ((lane & 7) << 2) + ((lane >> 3) << 5) + (P << 7);
    const int r0 = (k << 6) + (m << 1);    // 32*(2k) + 2m

    // Sign mask for the a2 mix: v=0 half negates sa (computed pre-sincos,
    // integer pipe, off the FP critical path).
    const unsigned sgn_mask = ((lane & 8) ^ 8) << 28;   // v==0 -> 0x80000000

    const float* base  = rho + r0 * 1024 + c;
    float*       obase = out + r0 * 1024 + c;

    // Rows: y00=r0 (i1=0,j1=0), y01=r0+1 (j1=1), y10=r0+32 (i1=1), y11=r0+33.
    // __ldcg: skip L1 fill (flushed per launch, single-use lines).
    float4 y00 = __ldcg(reinterpret_cast<const float4*>(base));
    float4 y01 = __ldcg(reinterpret_cast<const float4*>(base + 1024));
    float4 y10 = __ldcg(reinterpret_cast<const float4*>(base + 32768));
    float4 y11 = __ldcg(reinterpret_cast<const float4*>(base + 33792));

    // Angle math (overlaps the loads above).
    const float suma = (A0.x + A0.z) + (A1.x + A1.z)
                     + (A2.x + A2.z) + (A3.x + A3.z);
    const float sumb = (A0.y + A0.w) + (A1.y + A1.w)
                     + (A2.y + A2.w) + (A3.y + A3.w);
    float ca, sa, cb, sb;
    __sincosf(suma, &sa, &ca);
    __sincosf(sumb, &sb, &cb);
    const float sg = __int_as_float(__float_as_int(sa) ^ (int)sgn_mask);

    // a2 mix first, per row as each load lands: shuffle latency overlaps the
    // remaining in-flight loads instead of sitting on the tail.
    mix8(y00, ca, sg);
    mix8(y01, ca, sg);
    mix8(y10, ca, sg);
    mix8(y11, ca, sg);

    // a1 mix (ca,sa): rows r0 <-> r0+32
    rot(y00.x, y10.x, ca, sa);  rot(y00.y, y10.y, ca, sa);
    rot(y00.z, y10.z, ca, sa);  rot(y00.w, y10.w, ca, sa);
    rot(y01.x, y11.x, ca, sa);  rot(y01.y, y11.y, ca, sa);
    rot(y01.z, y11.z, ca, sa);  rot(y01.w, y11.w, ca, sa);

    // b1 mix (cb,sb): rows r0 <-> r0+1
    rot(y00.x, y01.x, cb, sb);  rot(y00.y, y01.y, cb, sb);
    rot(y00.z, y01.z, cb, sb);  rot(y00.w, y01.w, cb, sb);
    rot(y10.x, y11.x, cb, sb);  rot(y10.y, y11.y, cb, sb);
    rot(y10.z, y11.z, cb, sb);  rot(y10.w, y11.w, cb, sb);

    // b2 mix (cb,sb): col pairs (c,c+1),(c+2,c+3); store rows as finalized.
    rot(y00.x, y00.y, cb, sb);  rot(y00.z, y00.w, cb, sb);
    *reinterpret_cast<float4*>(obase) = y00;
    rot(y01.x, y01.y, cb, sb);  rot(y01.z, y01.w, cb, sb);
    *reinterpret_cast<float4*>(obase + 1024) = y01;
    rot(y10.x, y10.y, cb, sb);  rot(y10.z, y10.w, cb, sb);
    *reinterpret_cast<float4*>(obase + 32768) = y10;
    rot(y11.x, y11.y, cb, sb);  rot(y11.z, y11.w, cb, sb);
    *reinterpret_cast<float4*>(obase + 33792) = y11;
}

extern "C" void kernel_launch(void* const* d_in, const int* in_sizes, int n_in,
                              void* d_out, int out_size)
{
    const float* rho    = (const float*)d_in[0];  // input_state [1024,1024] f32
    const float* angles = (const float*)d_in[1];  // [16] f32
    // d_in[2..4]: cos/sin/id stacks — analytically folded away, never read.
    float* out = (float*)d_out;

    // 65536 threads in a single wave: 128 blocks x 512 threads (1 CTA/SM).
    vqc_bs_density_kernel<<<128, 512>>>(rho, angles, out);
}

// round 12
// speedup vs baseline: 1.0337x; 1.0337x over previous
#include <cuda_runtime.h>

// VQC_Registers_BS_density — analytic collapse:
// State index s = 32*a + b. Even layers rotate a-pairs (2k,2k+1), odd layers
// rotate b-pairs (2m,2m+1); every 2x2 gate block B(theta) = R(theta - pi/2)
// is a rotation, same-pair rotations compose additively, and the 8 * (pi/2)
// offsets cancel (4*pi). The whole 16-layer circuit is therefore
//   U = R_a(sum theta_even) (x) R_b(sum theta_odd)
// and rho' = U rho U^T factors into four independent pairwise Givens mixes on
// the tensor indices (a1, b1, a2, b2) of rho[32,32,32,32]. Total traffic 8 MB;
// the 48 MB of gate-matrix inputs are never read. (Reference: 16 dense
// 1024x1024 conjugations, ~34 GFLOP + ~100 MB traffic.)
//
// TERMINAL configuration (11 measured rounds): 65536 threads = 128 blocks x
// 512 (single wave, 1 CTA/SM), 4x LDG.128 + 4x STG.128 per thread, uniform
// angle loads issued before the data loads (sum + MUFU sincos hidden under
// load latency), cross-lane a2 mix (shfl_xor 8) applied per row as loads
// land, local a1/b1/b2 mixes after, rows stored as finalized, branchless
// sign via bit-XOR, __ldcg single-use loads, __stcg streaming stores.
//
// Measured floor: wall 6.6-6.9 us with +/-0.25 us noise on IDENTICAL code
// (3 repeats); ncu kernel 5.1-5.6 us with its own ramp noise; all pipes <11%;
// duration insensitive to +/-50% instruction count across 10 structural
// variants (occupancy 13-37%, 1-4 CTAs/SM, shuffle vs shuffle-free, 1 vs 2
// kernels, 3 grid shapes). Remaining cost = launch/clock-ramp + one 8 MB
// memory round trip + graph replay overhead.

__device__ __forceinline__ void rot(float& a, float& b, float c, float s)
{
    float t = c * a - s * b;
    b = s * a + c * b;
    a = t;
}

// a2 Givens mix across lane^8: e' = ca*e + sg*partner (sg = +/-sa by v-half).
__device__ __forceinline__ void mix8(float4& y, float ca, float sg)
{
    float p;
    p = __shfl_xor_sync(0xffffffffu, y.x, 8);  y.x = ca * y.x + sg * p;
    p = __shfl_xor_sync(0xffffffffu, y.y, 8);  y.y = ca * y.y + sg * p;
    p = __shfl_xor_sync(0xffffffffu, y.z, 8);  y.z = ca * y.z + sg * p;
    p = __shfl_xor_sync(0xffffffffu, y.w, 8);  y.w = ca * y.w + sg * p;
}

__global__ __launch_bounds__(512) void vqc_bs_density_kernel(
    const float* __restrict__ rho,
    const float* __restrict__ angles,
    float* __restrict__ out)
{
    const int tid = blockIdx.x * 512 + threadIdx.x;  // 0..65535

    // Composed angles first (uniform; 4x LDG.128 broadcast). Their latency
    // and the sum/sincos chain overlap the data loads issued just below.
    const float4* a4 = reinterpret_cast<const float4*>(angles);
    const float4 A0 = __ldg(a4 + 0), A1 = __ldg(a4 + 1);
    const float4 A2 = __ldg(a4 + 2), A3 = __ldg(a4 + 3);

    // lane bits: [0:3)=u (float4 within 32-col half), [3]=v (a2 half).
    const int lane = tid & 31;
    const int P    = (tid >> 5) & 7;
    const int m    = (tid >> 8) & 15;
    const int k    = tid >> 12;

    const int c  = ((lane & 7) << 2) + ((lane >> 3) << 5) + (P << 7);
    const int r0 = (k << 6) + (m << 1);    // 32*(2k) + 2m

    // Sign mask for the a2 mix: v=0 half negates sa (computed pre-sincos,
    // integer pipe, off the FP critical path).
    const unsigned sgn_mask = ((lane & 8) ^ 8) << 28;   // v==0 -> 0x80000000

    const float* base  = rho + r0 * 1024 + c;
    float*       obase = out + r0 * 1024 + c;

    // Rows: y00=r0 (i1=0,j1=0), y01=r0+1 (j1=1), y10=r0+32 (i1=1), y11=r0+33.
    // __ldcg: skip L1 fill (flushed per launch, single-use lines).
    float4 y00 = __ldcg(reinterpret_cast<const float4*>(base));
    float4 y01 = __ldcg(reinterpret_cast<const float4*>(base + 1024));
    float4 y10 = __ldcg(reinterpret_cast<const float4*>(base + 32768));
    float4 y11 = __ldcg(reinterpret_cast<const float4*>(base + 33792));

    // Angle math (overlaps the loads above).
    const float suma = (A0.x + A0.z) + (A1.x + A1.z)
                     + (A2.x + A2.z) + (A3.x + A3.z);
    const float sumb = (A0.y + A0.w) + (A1.y + A1.w)
                     + (A2.y + A2.w) + (A3.y + A3.w);
    float ca, sa, cb, sb;
    __sincosf(suma, &sa, &ca);
    __sincosf(sumb, &sb, &cb);
    const float sg = __int_as_float(__float_as_int(sa) ^ (int)sgn_mask);

    // a2 mix first, per row as each load lands: shuffle latency overlaps the
    // remaining in-flight loads instead of sitting on the tail.
    mix8(y00, ca, sg);
    mix8(y01, ca, sg);
    mix8(y10, ca, sg);
    mix8(y11, ca, sg);

    // a1 mix (ca,sa): rows r0 <-> r0+32
    rot(y00.x, y10.x, ca, sa);  rot(y00.y, y10.y, ca, sa);
    rot(y00.z, y10.z, ca, sa);  rot(y00.w, y10.w, ca, sa);
    rot(y01.x, y11.x, ca, sa);  rot(y01.y, y11.y, ca, sa);
    rot(y01.z, y11.z, ca, sa);  rot(y01.w, y11.w, ca, sa);

    // b1 mix (cb,sb): rows r0 <-> r0+1
    rot(y00.x, y01.x, cb, sb);  rot(y00.y, y01.y, cb, sb);
    rot(y00.z, y01.z, cb, sb);  rot(y00.w, y01.w, cb, sb);
    rot(y10.x, y11.x, cb, sb);  rot(y10.y, y11.y, cb, sb);
    rot(y10.z, y11.z, cb, sb);  rot(y10.w, y11.w, cb, sb);

    // b2 mix (cb,sb): col pairs (c,c+1),(c+2,c+3); store rows as finalized.
    // __stcg: streaming stores — output is write-once, never re-read here.
    rot(y00.x, y00.y, cb, sb);  rot(y00.z, y00.w, cb, sb);
    __stcg(reinterpret_cast<float4*>(obase), y00);
    rot(y01.x, y01.y, cb, sb);  rot(y01.z, y01.w, cb, sb);
    __stcg(reinterpret_cast<float4*>(obase + 1024), y01);
    rot(y10.x, y10.y, cb, sb);  rot(y10.z, y10.w, cb, sb);
    __stcg(reinterpret_cast<float4*>(obase + 32768), y10);
    rot(y11.x, y11.y, cb, sb);  rot(y11.z, y11.w, cb, sb);
    __stcg(reinterpret_cast<float4*>(obase + 33792), y11);
}

extern "C" void kernel_launch(void* const* d_in, const int* in_sizes, int n_in,
                              void* d_out, int out_size)
{
    const float* rho    = (const float*)d_in[0];  // input_state [1024,1024] f32
    const float* angles = (const float*)d_in[1];  // [16] f32
    // d_in[2..4]: cos/sin/id stacks — analytically folded away, never read.
    float* out = (float*)d_out;

    // 65536 threads in a single wave: 128 blocks x 512 threads (1 CTA/SM).
    vqc_bs_density_kernel<<<128, 512>>>(rho, angles, out);
}

// round 13
// speedup vs baseline: 1.0386x; 1.0048x over previous
#include <cuda_runtime.h>

// VQC_Registers_BS_density — analytic collapse:
// State index s = 32*a + b. Even layers rotate a-pairs (2k,2k+1), odd layers
// rotate b-pairs (2m,2m+1); every 2x2 gate block B(theta) = R(theta - pi/2)
// is a rotation, same-pair rotations compose additively, and the 8 * (pi/2)
// offsets cancel (4*pi). The whole 16-layer circuit is therefore
//   U = R_a(sum theta_even) (x) R_b(sum theta_odd)
// and rho' = U rho U^T factors into four independent pairwise Givens mixes on
// the tensor indices (a1, b1, a2, b2) of rho[32,32,32,32]. Total traffic 8 MB;
// the 48 MB of gate-matrix inputs are never read. (Reference: 16 dense
// 1024x1024 conjugations, ~34 GFLOP + ~100 MB traffic.)
//
// TERMINAL configuration (12 measured rounds): 65536 threads = 128 blocks x
// 512 (single wave, 1 CTA/SM), 4x LDG.128 + 4x STG.128 per thread, uniform
// angle loads issued before the data loads (sum + MUFU sincos hidden under
// load latency), cross-lane a2 mix (shfl_xor 8) applied per row as loads
// land, local a1/b1/b2 mixes after, rows stored as finalized, branchless
// sign via bit-XOR, __ldcg single-use loads, __stcg streaming stores.
//
// Measured floor: wall 6.62-6.91 us with +/-0.25 us noise on IDENTICAL code
// (4 repeats); ncu kernel 5.1-5.6 us with its own clock-ramp noise; all
// pipes <11%; duration insensitive to +/-50% instruction count across 10
// structural variants (occupancy 13-37%, 1-4 CTAs/SM, shuffle vs
// shuffle-free, 1 vs 2 kernels, 3 grid shapes, cache-policy bits).
// Remaining cost = launch/clock-ramp + one compulsory 8 MB memory round
// trip + graph replay overhead. Held unchanged — further perturbation is
// noise-fitting.

__device__ __forceinline__ void rot(float& a, float& b, float c, float s)
{
    float t = c * a - s * b;
    b = s * a + c * b;
    a = t;
}

// a2 Givens mix across lane^8: e' = ca*e + sg*partner (sg = +/-sa by v-half).
__device__ __forceinline__ void mix8(float4& y, float ca, float sg)
{
    float p;
    p = __shfl_xor_sync(0xffffffffu, y.x, 8);  y.x = ca * y.x + sg * p;
    p = __shfl_xor_sync(0xffffffffu, y.y, 8);  y.y = ca * y.y + sg * p;
    p = __shfl_xor_sync(0xffffffffu, y.z, 8);  y.z = ca * y.z + sg * p;
    p = __shfl_xor_sync(0xffffffffu, y.w, 8);  y.w = ca * y.w + sg * p;
}

__global__ __launch_bounds__(512) void vqc_bs_density_kernel(
    const float* __restrict__ rho,
    const float* __restrict__ angles,
    float* __restrict__ out)
{
    const int tid = blockIdx.x * 512 + threadIdx.x;  // 0..65535

    // Composed angles first (uniform; 4x LDG.128 broadcast). Their latency
    // and the sum/sincos chain overlap the data loads issued just below.
    const float4* a4 = reinterpret_cast<const float4*>(angles);
    const float4 A0 = __ldg(a4 + 0), A1 = __ldg(a4 + 1);
    const float4 A2 = __ldg(a4 + 2), A3 = __ldg(a4 + 3);

    // lane bits: [0:3)=u (float4 within 32-col half), [3]=v (a2 half).
    const int lane = tid & 31;
    const int P    = (tid >> 5) & 7;
    const int m    = (tid >> 8) & 15;
    const int k    = tid >> 12;

    const int c  = ((lane & 7) << 2) + ((lane >> 3) << 5) + (P << 7);
    const int r0 = (k << 6) + (m << 1);    // 32*(2k) + 2m

    // Sign mask for the a2 mix: v=0 half negates sa (computed pre-sincos,
    // integer pipe, off the FP critical path).
    const unsigned sgn_mask = ((lane & 8) ^ 8) << 28;   // v==0 -> 0x80000000

    const float* base  = rho + r0 * 1024 + c;
    float*       obase = out + r0 * 1024 + c;

    // Rows: y00=r0 (i1=0,j1=0), y01=r0+1 (j1=1), y10=r0+32 (i1=1), y11=r0+33.
    // __ldcg: skip L1 fill (flushed per launch, single-use lines).
    float4 y00 = __ldcg(reinterpret_cast<const float4*>(base));
    float4 y01 = __ldcg(reinterpret_cast<const float4*>(base + 1024));
    float4 y10 = __ldcg(reinterpret_cast<const float4*>(base + 32768));
    float4 y11 = __ldcg(reinterpret_cast<const float4*>(base + 33792));

    // Angle math (overlaps the loads above).
    const float suma = (A0.x + A0.z) + (A1.x + A1.z)
                     + (A2.x + A2.z) + (A3.x + A3.z);
    const float sumb = (A0.y + A0.w) + (A1.y + A1.w)
                     + (A2.y + A2.w) + (A3.y + A3.w);
    float ca, sa, cb, sb;
    __sincosf(suma, &sa, &ca);
    __sincosf(sumb, &sb, &cb);
    const float sg = __int_as_float(__float_as_int(sa) ^ (int)sgn_mask);

    // a2 mix first, per row as each load lands: shuffle latency overlaps the
    // remaining in-flight loads instead of sitting on the tail.
    mix8(y00, ca, sg);
    mix8(y01, ca, sg);
    mix8(y10, ca, sg);
    mix8(y11, ca, sg);

    // a1 mix (ca,sa): rows r0 <-> r0+32
    rot(y00.x, y10.x, ca, sa);  rot(y00.y, y10.y, ca, sa);
    rot(y00.z, y10.z, ca, sa);  rot(y00.w, y10.w, ca, sa);
    rot(y01.x, y11.x, ca, sa);  rot(y01.y, y11.y, ca, sa);
    rot(y01.z, y11.z, ca, sa);  rot(y01.w, y11.w, ca, sa);

    // b1 mix (cb,sb): rows r0 <-> r0+1
    rot(y00.x, y01.x, cb, sb);  rot(y00.y, y01.y, cb, sb);
    rot(y00.z, y01.z, cb, sb);  rot(y00.w, y01.w, cb, sb);
    rot(y10.x, y11.x, cb, sb);  rot(y10.y, y11.y, cb, sb);
    rot(y10.z, y11.z, cb, sb);  rot(y10.w, y11.w, cb, sb);

    // b2 mix (cb,sb): col pairs (c,c+1),(c+2,c+3); store rows as finalized.
    // __stcg: streaming stores — output is write-once, never re-read here.
    rot(y00.x, y00.y, cb, sb);  rot(y00.z, y00.w, cb, sb);
    __stcg(reinterpret_cast<float4*>(obase), y00);
    rot(y01.x, y01.y, cb, sb);  rot(y01.z, y01.w, cb, sb);
    __stcg(reinterpret_cast<float4*>(obase + 1024), y01);
    rot(y10.x, y10.y, cb, sb);  rot(y10.z, y10.w, cb, sb);
    __stcg(reinterpret_cast<float4*>(obase + 32768), y10);
    rot(y11.x, y11.y, cb, sb);  rot(y11.z, y11.w, cb, sb);
    __stcg(reinterpret_cast<float4*>(obase + 33792), y11);
}

extern "C" void kernel_launch(void* const* d_in, const int* in_sizes, int n_in,
                              void* d_out, int out_size)
{
    const float* rho    = (const float*)d_in[0];  // input_state [1024,1024] f32
    const float* angles = (const float*)d_in[1];  // [16] f32
    // d_in[2..4]: cos/sin/id stacks — analytically folded away, never read.
    float* out = (float*)d_out;

    // 65536 threads in a single wave: 128 blocks x 512 threads (1 CTA/SM).
    vqc_bs_density_kernel<<<128, 512>>>(rho, angles, out);
}